// round 1
// baseline (speedup 1.0000x reference)
#include <cuda_runtime.h>
#include <cstdint>
#include <cmath>

// ---------------------------------------------------------------------------
// GraphSageLayer: B=4, N=4096, D_IN=128, REP=128, D_OUT=128
//
// Pipeline (all GEMMs via tf32 mma.sync m16n8k8, fp32 accumulate):
//   1) proj x3 : rep = ELU(nodes @ W^T + b)      M=16384, N=128, K=128  (TN, B transposed)
//   2) agg_in  : upd[:,0:128]   = adj   @ in_rep M=4096,  N=128, K=4096 (per batch)
//   3) agg_out : upd[:,256:384] = adj^T @ out_rep (A transposed at smem-stage time)
//   4) final   : out = tanh(upd @ W_upd^T + b)   M=16384, N=128, K=384
// ---------------------------------------------------------------------------

#define APAD 20    // As row pad (words): conflict-free frag loads, 16B-aligned rows
#define BPAD 136   // Bs row pad (words): conflict-free frag loads, 16B-aligned rows

// static scratch (allocation-free rule)
__device__ float g_in_rep [4l * 4096 * 128];   // 8 MB
__device__ float g_out_rep[4l * 4096 * 128];   // 8 MB
__device__ float g_upd    [4l * 4096 * 384];   // 25 MB

__device__ __forceinline__ uint32_t f2tf32(float f) {
    uint32_t u;
    asm("cvt.rna.tf32.f32 %0, %1;" : "=r"(u) : "f"(f));
    return u;
}

enum { EPI_NONE = 0, EPI_ELU = 1, EPI_TANH = 2 };

// C[m,n] = sum_k opA(A)[m,k] * opB(B)[k,n]
//   TA=false: opA(A)[m,k] = A[m*lda + k]     (row-major MxK)
//   TA=true : opA(A)[m,k] = A[k*lda + m]     (transposed read)
//   TB=false: opB(B)[k,n] = B[k*ldb + n]     (row-major KxN)
//   TB=true : opB(B)[k,n] = B[n*ldb + k]     (row-major NxK, i.e. TN gemm)
// CTA tile: 128(M) x 128(N), BK=16, 256 threads = 8 warps (4x2),
// warp tile 32x64 = 2 x 8 m16n8 mma tiles.
template<bool TA, bool TTB, int EPI>
__global__ __launch_bounds__(256)
void gemm_tn(const float* __restrict__ A, int lda, long aStride,
             const float* __restrict__ B, int ldb, long bStride,
             const float* __restrict__ bias,
             float* __restrict__ D, int ldd, int dOff, long dStride,
             int K)
{
    __shared__ uint32_t As[2][128][APAD];  // tf32 bits, [m][k]
    __shared__ uint32_t Bs[2][16][BPAD];   // tf32 bits, [k][n]

    const int batch = blockIdx.y;
    A += (long)batch * aStride;
    B += (long)batch * bStride;
    D += (long)batch * dStride;

    const int m0   = blockIdx.x * 128;
    const int tid  = threadIdx.x;
    const int lane = tid & 31;
    const int warp = tid >> 5;
    const int wm   = warp >> 1;   // 0..3
    const int wn   = warp & 1;    // 0..1
    const int g    = lane >> 2;   // groupID
    const int t    = lane & 3;    // threadID_in_group

    float acc[2][8][4];
    #pragma unroll
    for (int i = 0; i < 2; i++)
        #pragma unroll
        for (int j = 0; j < 8; j++)
            #pragma unroll
            for (int l = 0; l < 4; l++) acc[i][j][l] = 0.f;

    // staging-thread index math (256 threads, 2 float4 per operand per thread)
    const int am  = tid >> 2;          // A !T : rows tid/4, tid/4+64
    const int ak4 = (tid & 3) * 4;     //        k-quad
    const int ak  = tid >> 5;          // A  T : k rows tid/32, +8
    const int am4 = (tid & 31) * 4;    //        m-quad (contiguous gmem)
    const int bk  = tid >> 5;          // B !T : k rows tid/32, +8
    const int bn4 = (tid & 31) * 4;    //        n-quad
    const int bn  = tid >> 2;          // B  T : n rows tid/4, +64
    const int bk4 = (tid & 3) * 4;     //        k-quad

    float4 ra[2], rb[2];

    auto loadRegs = [&](int k0) {
        if (!TA) {
            ra[0] = *(const float4*)(A + (long)(m0 + am)      * lda + k0 + ak4);
            ra[1] = *(const float4*)(A + (long)(m0 + am + 64) * lda + k0 + ak4);
        } else {
            ra[0] = *(const float4*)(A + (long)(k0 + ak)     * lda + m0 + am4);
            ra[1] = *(const float4*)(A + (long)(k0 + ak + 8) * lda + m0 + am4);
        }
        if (!TTB) {
            rb[0] = *(const float4*)(B + (long)(k0 + bk)     * ldb + bn4);
            rb[1] = *(const float4*)(B + (long)(k0 + bk + 8) * ldb + bn4);
        } else {
            rb[0] = *(const float4*)(B + (long)bn        * ldb + k0 + bk4);
            rb[1] = *(const float4*)(B + (long)(bn + 64) * ldb + k0 + bk4);
        }
    };

    auto stsRegs = [&](int buf) {
        if (!TA) {
            uint4 u0 = { f2tf32(ra[0].x), f2tf32(ra[0].y), f2tf32(ra[0].z), f2tf32(ra[0].w) };
            uint4 u1 = { f2tf32(ra[1].x), f2tf32(ra[1].y), f2tf32(ra[1].z), f2tf32(ra[1].w) };
            *(uint4*)&As[buf][am][ak4]      = u0;
            *(uint4*)&As[buf][am + 64][ak4] = u1;
        } else {
            As[buf][am4 + 0][ak]     = f2tf32(ra[0].x);
            As[buf][am4 + 1][ak]     = f2tf32(ra[0].y);
            As[buf][am4 + 2][ak]     = f2tf32(ra[0].z);
            As[buf][am4 + 3][ak]     = f2tf32(ra[0].w);
            As[buf][am4 + 0][ak + 8] = f2tf32(ra[1].x);
            As[buf][am4 + 1][ak + 8] = f2tf32(ra[1].y);
            As[buf][am4 + 2][ak + 8] = f2tf32(ra[1].z);
            As[buf][am4 + 3][ak + 8] = f2tf32(ra[1].w);
        }
        if (!TTB) {
            uint4 u0 = { f2tf32(rb[0].x), f2tf32(rb[0].y), f2tf32(rb[0].z), f2tf32(rb[0].w) };
            uint4 u1 = { f2tf32(rb[1].x), f2tf32(rb[1].y), f2tf32(rb[1].z), f2tf32(rb[1].w) };
            *(uint4*)&Bs[buf][bk][bn4]     = u0;
            *(uint4*)&Bs[buf][bk + 8][bn4] = u1;
        } else {
            Bs[buf][bk4 + 0][bn]      = f2tf32(rb[0].x);
            Bs[buf][bk4 + 1][bn]      = f2tf32(rb[0].y);
            Bs[buf][bk4 + 2][bn]      = f2tf32(rb[0].z);
            Bs[buf][bk4 + 3][bn]      = f2tf32(rb[0].w);
            Bs[buf][bk4 + 0][bn + 64] = f2tf32(rb[1].x);
            Bs[buf][bk4 + 1][bn + 64] = f2tf32(rb[1].y);
            Bs[buf][bk4 + 2][bn + 64] = f2tf32(rb[1].z);
            Bs[buf][bk4 + 3][bn + 64] = f2tf32(rb[1].w);
        }
    };

    auto compute = [&](int buf) {
        #pragma unroll
        for (int ks = 0; ks < 2; ks++) {
            const int k8 = ks * 8;
            uint32_t af[2][4];
            #pragma unroll
            for (int mt = 0; mt < 2; mt++) {
                int mr = wm * 32 + mt * 16 + g;
                af[mt][0] = As[buf][mr][k8 + t];
                af[mt][1] = As[buf][mr + 8][k8 + t];
                af[mt][2] = As[buf][mr][k8 + t + 4];
                af[mt][3] = As[buf][mr + 8][k8 + t + 4];
            }
            uint32_t bf[8][2];
            #pragma unroll
            for (int nt = 0; nt < 8; nt++) {
                int nc = wn * 64 + nt * 8 + g;
                bf[nt][0] = Bs[buf][k8 + t][nc];
                bf[nt][1] = Bs[buf][k8 + t + 4][nc];
            }
            #pragma unroll
            for (int mt = 0; mt < 2; mt++)
                #pragma unroll
                for (int nt = 0; nt < 8; nt++) {
                    asm volatile(
                        "mma.sync.aligned.m16n8k8.row.col.f32.tf32.tf32.f32 "
                        "{%0,%1,%2,%3}, {%4,%5,%6,%7}, {%8,%9}, {%0,%1,%2,%3};\n"
                        : "+f"(acc[mt][nt][0]), "+f"(acc[mt][nt][1]),
                          "+f"(acc[mt][nt][2]), "+f"(acc[mt][nt][3])
                        : "r"(af[mt][0]), "r"(af[mt][1]), "r"(af[mt][2]), "r"(af[mt][3]),
                          "r"(bf[nt][0]), "r"(bf[nt][1]));
                }
        }
    };

    const int nk = K / 16;
    loadRegs(0);
    int buf = 0;
    for (int kt = 0; kt < nk; kt++) {
        stsRegs(buf);
        __syncthreads();              // single barrier/iter is sufficient (double buffer)
        if (kt + 1 < nk) loadRegs((kt + 1) * 16);
        compute(buf);
        buf ^= 1;
    }

    // epilogue
    #pragma unroll
    for (int mt = 0; mt < 2; mt++) {
        #pragma unroll
        for (int nt = 0; nt < 8; nt++) {
            const int row = m0 + wm * 32 + mt * 16 + g;
            const int col = wn * 64 + nt * 8 + 2 * t;
            float x0 = acc[mt][nt][0], x1 = acc[mt][nt][1];
            float x2 = acc[mt][nt][2], x3 = acc[mt][nt][3];
            if (EPI != EPI_NONE) {
                const float b0 = __ldg(bias + col);
                const float b1 = __ldg(bias + col + 1);
                x0 += b0; x1 += b1; x2 += b0; x3 += b1;
                if (EPI == EPI_ELU) {
                    x0 = x0 > 0.f ? x0 : expm1f(x0);
                    x1 = x1 > 0.f ? x1 : expm1f(x1);
                    x2 = x2 > 0.f ? x2 : expm1f(x2);
                    x3 = x3 > 0.f ? x3 : expm1f(x3);
                } else {
                    x0 = tanhf(x0); x1 = tanhf(x1);
                    x2 = tanhf(x2); x3 = tanhf(x3);
                }
            }
            *(float2*)&D[(long)row       * ldd + dOff + col] = make_float2(x0, x1);
            *(float2*)&D[(long)(row + 8) * ldd + dOff + col] = make_float2(x2, x3);
        }
    }
}

extern "C" void kernel_launch(void* const* d_in, const int* in_sizes, int n_in,
                              void* d_out, int out_size)
{
    const float* nodes  = (const float*)d_in[0];
    const float* adj    = (const float*)d_in[1];
    const float* W_in   = (const float*)d_in[2];
    const float* b_in   = (const float*)d_in[3];
    const float* W_out  = (const float*)d_in[4];
    const float* b_out  = (const float*)d_in[5];
    const float* W_node = (const float*)d_in[6];
    const float* b_node = (const float*)d_in[7];
    const float* W_upd  = (const float*)d_in[8];
    const float* b_upd  = (const float*)d_in[9];
    float* out = (float*)d_out;

    float *in_rep, *out_rep, *upd;
    cudaGetSymbolAddress((void**)&in_rep,  g_in_rep);
    cudaGetSymbolAddress((void**)&out_rep, g_out_rep);
    cudaGetSymbolAddress((void**)&upd,     g_upd);

    const dim3 blk(256);
    const long NN = 4096l * 4096;
    const long NR = 4096l * 128;
    const long NU = 4096l * 384;

    // 1) projections + ELU (M=16384, K=128); node_rep goes straight into upd[:,128:256]
    gemm_tn<false, true, EPI_ELU><<<dim3(128, 1), blk>>>(
        nodes, 128, 0, W_in, 128, 0, b_in, in_rep, 128, 0, 0, 128);
    gemm_tn<false, true, EPI_ELU><<<dim3(128, 1), blk>>>(
        nodes, 128, 0, W_node, 128, 0, b_node, upd, 384, 128, 0, 128);
    gemm_tn<false, true, EPI_ELU><<<dim3(128, 1), blk>>>(
        nodes, 128, 0, W_out, 128, 0, b_out, out_rep, 128, 0, 0, 128);

    // 2) in_agg = adj @ in_rep  -> upd[:, 0:128]
    gemm_tn<false, false, EPI_NONE><<<dim3(32, 4), blk>>>(
        adj, 4096, NN, in_rep, 128, NR, nullptr, upd, 384, 0, NU, 4096);

    // 3) out_agg = adj^T @ out_rep -> upd[:, 256:384]
    gemm_tn<true, false, EPI_NONE><<<dim3(32, 4), blk>>>(
        adj, 4096, NN, out_rep, 128, NR, nullptr, upd, 384, 256, NU, 4096);

    // 4) out = tanh(upd @ W_upd^T + b_upd)  (M=16384, K=384)
    gemm_tn<false, true, EPI_TANH><<<dim3(128, 1), blk>>>(
        upd, 384, 0, W_upd, 384, 0, b_upd, out, 128, 0, 0, 384);
}

// round 2
// speedup vs baseline: 1.2388x; 1.2388x over previous
#include <cuda_runtime.h>
#include <cstdint>
#include <cmath>

// ---------------------------------------------------------------------------
// GraphSageLayer: B=4, N=4096, D_IN=128, REP=128, D_OUT=128
//
// All GEMMs: tf32 mma.sync m16n8k8, fp32 accumulate.
// CTA tile 64(M) x 128(N), BK=16, 256 thr = 8 warps (2m x 4n), warp 32x32.
// 2 CTAs/SM (regs ~90, smem ~24KB) -> 16 warps/SM for latency hiding.
//
//   1) proj x3 (one launch, grid.z=3): rep = ELU(nodes @ W^T + b)
//   2) agg_in  : upd[:,0:128]   = adj   @ in_rep   (K=4096, 256 CTAs)
//   3) agg_out : upd[:,256:384] = adj^T @ out_rep  (transposed-A staging)
//   4) final   : out = tanh(upd @ W_upd^T + b)     (K=384)
// ---------------------------------------------------------------------------

#define AROW 20    // As row length in words (16 k + 4 pad): frag banks (20g+t) injective
#define BROW 136   // Bs row length in words (128 n + 8 pad): frag banks (8t+g+..) injective

__device__ float g_in_rep [4l * 4096 * 128];   // 8 MB
__device__ float g_out_rep[4l * 4096 * 128];   // 8 MB
__device__ float g_upd    [4l * 4096 * 384];   // 24 MB

__device__ __forceinline__ uint32_t f2tf32(float f) {
    uint32_t u;
    asm("cvt.rna.tf32.f32 %0, %1;" : "=r"(u) : "f"(f));
    return u;
}

enum { EPI_NONE = 0, EPI_ELU = 1, EPI_TANH = 2 };

// C[m,n] = sum_k opA(A)[m,k] * opB(B)[k,n]
//   TA=false: opA(A)[m,k] = A[m*lda + k]   TA=true: A[k*lda + m]
//   TTB=false: opB(B)[k,n] = B[k*ldb + n]  TTB=true: B[n*ldb + k]
template<bool TA, bool TTB, int EPI>
__device__ __forceinline__ void gemm64(
    const float* __restrict__ A, int lda,
    const float* __restrict__ B, int ldb,
    const float* __restrict__ bias,
    float* __restrict__ D, int ldd, int dOff,
    int K, int m0)
{
    __shared__ uint32_t As[2][64][AROW];
    __shared__ uint32_t Bs[2][16][BROW];

    const int tid  = threadIdx.x;
    const int lane = tid & 31;
    const int warp = tid >> 5;
    const int wm   = warp >> 2;   // 0..1  (32 rows each)
    const int wn   = warp & 3;    // 0..3  (32 cols each)
    const int g    = lane >> 2;   // groupID 0..7
    const int t    = lane & 3;    // thread-in-group 0..3

    float acc[2][4][4];
    #pragma unroll
    for (int i = 0; i < 2; i++)
        #pragma unroll
        for (int j = 0; j < 4; j++)
            #pragma unroll
            for (int l = 0; l < 4; l++) acc[i][j][l] = 0.f;

    // staging indices
    const int am   = tid >> 2;        // A !T: row 0..63
    const int ak4  = (tid & 3) * 4;   //       k quad
    const int akr  = tid >> 4;        // A  T: k row 0..15
    const int amc  = tid & 15;        //       m col base (strided by 16)
    const int bk   = tid >> 5;        // B !T: k rows bk, bk+8
    const int bn4  = lane * 4;        //       n quad (contiguous 128)
    const int bn   = tid >> 2;        // B  T: n rows bn, bn+64
    const int bk4  = (tid & 3) * 4;   //       k quad

    float4 ra4, rb[2];
    float  ras[4];

    auto loadRegs = [&](int k0) {
        if (!TA) {
            ra4 = *(const float4*)(A + (long)(m0 + am) * lda + k0 + ak4);
        } else {
            const float* ap = A + (long)(k0 + akr) * lda + m0 + amc;
            #pragma unroll
            for (int i = 0; i < 4; i++) ras[i] = ap[16 * i];
        }
        if (!TTB) {
            rb[0] = *(const float4*)(B + (long)(k0 + bk)     * ldb + bn4);
            rb[1] = *(const float4*)(B + (long)(k0 + bk + 8) * ldb + bn4);
        } else {
            rb[0] = *(const float4*)(B + (long)bn        * ldb + k0 + bk4);
            rb[1] = *(const float4*)(B + (long)(bn + 64) * ldb + k0 + bk4);
        }
    };

    auto stsRegs = [&](int buf) {
        if (!TA) {
            uint4 u = { f2tf32(ra4.x), f2tf32(ra4.y), f2tf32(ra4.z), f2tf32(ra4.w) };
            *(uint4*)&As[buf][am][ak4] = u;
        } else {
            #pragma unroll
            for (int i = 0; i < 4; i++)
                As[buf][amc + 16 * i][akr] = f2tf32(ras[i]);
        }
        if (!TTB) {
            uint4 u0 = { f2tf32(rb[0].x), f2tf32(rb[0].y), f2tf32(rb[0].z), f2tf32(rb[0].w) };
            uint4 u1 = { f2tf32(rb[1].x), f2tf32(rb[1].y), f2tf32(rb[1].z), f2tf32(rb[1].w) };
            *(uint4*)&Bs[buf][bk][bn4]     = u0;
            *(uint4*)&Bs[buf][bk + 8][bn4] = u1;
        } else {
            Bs[buf][bk4 + 0][bn]      = f2tf32(rb[0].x);
            Bs[buf][bk4 + 1][bn]      = f2tf32(rb[0].y);
            Bs[buf][bk4 + 2][bn]      = f2tf32(rb[0].z);
            Bs[buf][bk4 + 3][bn]      = f2tf32(rb[0].w);
            Bs[buf][bk4 + 0][bn + 64] = f2tf32(rb[1].x);
            Bs[buf][bk4 + 1][bn + 64] = f2tf32(rb[1].y);
            Bs[buf][bk4 + 2][bn + 64] = f2tf32(rb[1].z);
            Bs[buf][bk4 + 3][bn + 64] = f2tf32(rb[1].w);
        }
    };

    auto compute = [&](int buf) {
        #pragma unroll
        for (int ks = 0; ks < 2; ks++) {
            const int k8 = ks * 8;
            uint32_t af[2][4];
            #pragma unroll
            for (int mt = 0; mt < 2; mt++) {
                const int mr = wm * 32 + mt * 16 + g;
                af[mt][0] = As[buf][mr][k8 + t];
                af[mt][1] = As[buf][mr + 8][k8 + t];
                af[mt][2] = As[buf][mr][k8 + t + 4];
                af[mt][3] = As[buf][mr + 8][k8 + t + 4];
            }
            uint32_t bf[4][2];
            #pragma unroll
            for (int nt = 0; nt < 4; nt++) {
                const int nc = wn * 32 + nt * 8 + g;
                bf[nt][0] = Bs[buf][k8 + t][nc];
                bf[nt][1] = Bs[buf][k8 + t + 4][nc];
            }
            #pragma unroll
            for (int mt = 0; mt < 2; mt++)
                #pragma unroll
                for (int nt = 0; nt < 4; nt++) {
                    asm volatile(
                        "mma.sync.aligned.m16n8k8.row.col.f32.tf32.tf32.f32 "
                        "{%0,%1,%2,%3}, {%4,%5,%6,%7}, {%8,%9}, {%0,%1,%2,%3};\n"
                        : "+f"(acc[mt][nt][0]), "+f"(acc[mt][nt][1]),
                          "+f"(acc[mt][nt][2]), "+f"(acc[mt][nt][3])
                        : "r"(af[mt][0]), "r"(af[mt][1]), "r"(af[mt][2]), "r"(af[mt][3]),
                          "r"(bf[nt][0]), "r"(bf[nt][1]));
                }
        }
    };

    const int nk = K / 16;
    loadRegs(0);
    int buf = 0;
    for (int kt = 0; kt < nk; kt++) {
        stsRegs(buf);
        __syncthreads();
        if (kt + 1 < nk) loadRegs((kt + 1) * 16);
        compute(buf);
        buf ^= 1;
    }

    // epilogue
    #pragma unroll
    for (int mt = 0; mt < 2; mt++) {
        #pragma unroll
        for (int nt = 0; nt < 4; nt++) {
            const int row = m0 + wm * 32 + mt * 16 + g;
            const int col = wn * 32 + nt * 8 + 2 * t;
            float x0 = acc[mt][nt][0], x1 = acc[mt][nt][1];
            float x2 = acc[mt][nt][2], x3 = acc[mt][nt][3];
            if (EPI != EPI_NONE) {
                const float b0 = __ldg(bias + col);
                const float b1 = __ldg(bias + col + 1);
                x0 += b0; x1 += b1; x2 += b0; x3 += b1;
                if (EPI == EPI_ELU) {
                    x0 = x0 > 0.f ? x0 : expm1f(x0);
                    x1 = x1 > 0.f ? x1 : expm1f(x1);
                    x2 = x2 > 0.f ? x2 : expm1f(x2);
                    x3 = x3 > 0.f ? x3 : expm1f(x3);
                } else {
                    x0 = tanhf(x0); x1 = tanhf(x1);
                    x2 = tanhf(x2); x3 = tanhf(x3);
                }
            }
            *(float2*)&D[(long)row       * ldd + dOff + col] = make_float2(x0, x1);
            *(float2*)&D[(long)(row + 8) * ldd + dOff + col] = make_float2(x2, x3);
        }
    }
}

struct ProjArgs {
    const float* W0; const float* W1; const float* W2;
    const float* b0; const float* b1; const float* b2;
    float* D0; float* D1; float* D2;
    int ldd0, ldd1, ldd2;
    int off0, off1, off2;
};

// 3 projections in one launch: grid (256, 1, 3)
__global__ __launch_bounds__(256, 2)
void proj3_kernel(const float* __restrict__ nodes, ProjArgs p)
{
    const int z = blockIdx.z;
    const float* W; const float* b; float* D; int ldd, off;
    if (z == 0)      { W = p.W0; b = p.b0; D = p.D0; ldd = p.ldd0; off = p.off0; }
    else if (z == 1) { W = p.W1; b = p.b1; D = p.D1; ldd = p.ldd1; off = p.off1; }
    else             { W = p.W2; b = p.b2; D = p.D2; ldd = p.ldd2; off = p.off2; }
    gemm64<false, true, EPI_ELU>(nodes, 128, W, 128, b, D, ldd, off, 128, blockIdx.x * 64);
}

// aggregation: grid (64, 4)
template<bool TA>
__global__ __launch_bounds__(256, 2)
void agg_kernel(const float* __restrict__ adj, const float* __restrict__ rep,
                float* __restrict__ upd, int dOff)
{
    const int batch = blockIdx.y;
    gemm64<TA, false, EPI_NONE>(
        adj + (long)batch * 4096 * 4096, 4096,
        rep + (long)batch * 4096 * 128, 128,
        nullptr,
        upd + (long)batch * 4096 * 384, 384, dOff,
        4096, blockIdx.x * 64);
}

// final: grid (256)
__global__ __launch_bounds__(256, 2)
void final_kernel(const float* __restrict__ upd, const float* __restrict__ W,
                  const float* __restrict__ b, float* __restrict__ out)
{
    gemm64<false, true, EPI_TANH>(upd, 384, W, 384, b, out, 128, 0, 384, blockIdx.x * 64);
}

extern "C" void kernel_launch(void* const* d_in, const int* in_sizes, int n_in,
                              void* d_out, int out_size)
{
    const float* nodes  = (const float*)d_in[0];
    const float* adj    = (const float*)d_in[1];
    const float* W_in   = (const float*)d_in[2];
    const float* b_in   = (const float*)d_in[3];
    const float* W_out  = (const float*)d_in[4];
    const float* b_out  = (const float*)d_in[5];
    const float* W_node = (const float*)d_in[6];
    const float* b_node = (const float*)d_in[7];
    const float* W_upd  = (const float*)d_in[8];
    const float* b_upd  = (const float*)d_in[9];
    float* out = (float*)d_out;

    float *in_rep, *out_rep, *upd;
    cudaGetSymbolAddress((void**)&in_rep,  g_in_rep);
    cudaGetSymbolAddress((void**)&out_rep, g_out_rep);
    cudaGetSymbolAddress((void**)&upd,     g_upd);

    ProjArgs p;
    p.W0 = W_in;   p.b0 = b_in;   p.D0 = in_rep;  p.ldd0 = 128; p.off0 = 0;
    p.W1 = W_node; p.b1 = b_node; p.D1 = upd;     p.ldd1 = 384; p.off1 = 128;
    p.W2 = W_out;  p.b2 = b_out;  p.D2 = out_rep; p.ldd2 = 128; p.off2 = 0;

    // 1) three ELU projections, one launch
    proj3_kernel<<<dim3(256, 1, 3), 256>>>(nodes, p);

    // 2) in_agg = adj @ in_rep -> upd[:, 0:128]
    agg_kernel<false><<<dim3(64, 4), 256>>>(adj, in_rep, upd, 0);

    // 3) out_agg = adj^T @ out_rep -> upd[:, 256:384]
    agg_kernel<true><<<dim3(64, 4), 256>>>(adj, out_rep, upd, 256);

    // 4) out = tanh(upd @ W_upd^T + b_upd)
    final_kernel<<<256, 256>>>(upd, W_upd, b_upd, out);
}

// round 4
// speedup vs baseline: 1.7989x; 1.4521x over previous
#include <cuda_runtime.h>
#include <cuda_fp16.h>
#include <cstdint>
#include <cmath>

// ---------------------------------------------------------------------------
// GraphSageLayer: B=4, N=4096, D_IN=128, REP=128, D_OUT=128
// All GEMMs: fp16 mma.sync m16n8k16, fp32 accumulate (11-bit mantissa = tf32).
// CTA tile 64x128, BK=32, 256 thr = 8 warps (2m x 4n), warp 32x32, 2 CTA/SM.
// adj is scaled x4096 into fp16 (avoids subnormals), epilogue scales x1/4096.
//
//   proj3 (1 launch, z=3): in_rep/out_rep = ELU(nodes@W^T+b) as fp16 [n][128]
//                          node_rep -> upd[:,128:256] (fp32)
//   agg_in : upd[:,0:128]   = adj   @ in_rep   (K=4096)
//   agg_out: upd[:,256:384] = adj^T @ out_rep  (strided-A staging)
//   final  : out = tanh(upd @ W_upd^T + b)     (K=384)
// ---------------------------------------------------------------------------

#define AROW 20    // As row words (16 used): frag banks (20g+t) all-distinct
#define BROW 136   // Bs row words (128 used): frag banks (8t+g) all-distinct

__device__ __half g_in_rep [4l * 4096 * 128];   // 4 MB
__device__ __half g_out_rep[4l * 4096 * 128];   // 4 MB
__device__ float  g_upd    [4l * 4096 * 384];   // 24 MB

enum { A_F32_ROW = 0, A_F32_TRANS = 1 };
enum { B_F16_KN = 0, B_F32_NK = 1 };
enum { EPI_SCALE = 0, EPI_ELU = 1, EPI_TANH = 2 };

// pack2(a,b): low half = a, high half = b
__device__ __forceinline__ uint32_t pack2(float a, float b) {
    uint32_t r;
    asm("cvt.rn.f16x2.f32 %0, %1, %2;" : "=r"(r) : "f"(b), "f"(a));
    return r;
}

// ===========================================================================
// Shared GEMM core: C[64x128] tile, K in steps of 32.
//   ASRC: A_F32_ROW   -> A[m*lda + k]          (fp32, optional x4096)
//         A_F32_TRANS -> A[k*lda + m]          (fp32, optional x4096)
//   BSRC: B_F16_KN    -> Bh[k*ldb + n]         (fp16 row-major KxN)
//         B_F32_NK    -> Bf[n*ldb + k]         (fp32 row-major NxK, i.e. TN)
//   EPI : SCALE (x 1/4096, no bias) | ELU (+bias) | TANH (+bias)
//   HOUT: write fp16 (half2 packed) vs fp32
// SMEM words are half2 pairs packed along k.
// ===========================================================================
template<int ASRC, int BSRC, int EPI, bool HOUT>
__device__ __forceinline__ void gemm_core(
    const float* __restrict__ Af, int lda,
    const void* __restrict__ Bv, int ldb,
    const float* __restrict__ bias,
    void* __restrict__ Dv, int ldd, int dOff,
    int K, int m0)
{
    __shared__ uint32_t As[2][64][AROW];   // word(m, kk) = {A[m][2kk], A[m][2kk+1]}
    __shared__ uint32_t Bs[2][16][BROW];   // word(kk, n) = {B[2kk][n], B[2kk+1][n]}

    const int tid  = threadIdx.x;
    const int lane = tid & 31;
    const int warp = tid >> 5;
    const int wm   = warp >> 2;   // 0..1
    const int wn   = warp & 3;    // 0..3
    const int g    = lane >> 2;
    const int t    = lane & 3;

    constexpr float ASCALE = (EPI == EPI_SCALE) ? 4096.f : 1.f;

    float acc[2][4][4];
    #pragma unroll
    for (int i = 0; i < 2; i++)
        #pragma unroll
        for (int j = 0; j < 4; j++)
            #pragma unroll
            for (int l = 0; l < 4; l++) acc[i][j][l] = 0.f;

    // staging thread-index math
    const int m_a = tid >> 2, q_a = tid & 3;          // A row-major
    const int m_t = tid & 63, kk4 = (tid >> 6) * 4;   // A transposed
    const int qb  = tid & 31, kkb = (tid >> 5) * 2;   // B f16 KN (2 kk-words)
    const int kkw = tid & 15, nb  = (tid >> 4) * 8;   // B f32 NK

    float fa[8];
    uint2 rbh[4];
    float2 rbf[8];

    auto loadRegs = [&](int k0) {
        if (ASRC == A_F32_ROW) {
            const float4* p = (const float4*)(Af + (long)(m0 + m_a) * lda + k0 + 8 * q_a);
            float4 v0 = p[0], v1 = p[1];
            fa[0] = v0.x; fa[1] = v0.y; fa[2] = v0.z; fa[3] = v0.w;
            fa[4] = v1.x; fa[5] = v1.y; fa[6] = v1.z; fa[7] = v1.w;
        } else {
            const float* p = Af + (long)(k0 + 2 * kk4) * lda + m0 + m_t;
            #pragma unroll
            for (int i = 0; i < 8; i++) fa[i] = p[(long)i * lda];
        }
        if (BSRC == B_F16_KN) {
            const __half* Bh = (const __half*)Bv;
            #pragma unroll
            for (int i = 0; i < 4; i++)
                rbh[i] = *(const uint2*)(Bh + (long)(k0 + 2 * kkb + i) * ldb + 4 * qb);
        } else {
            const float* Bf = (const float*)Bv;
            #pragma unroll
            for (int i = 0; i < 8; i++)
                rbf[i] = *(const float2*)(Bf + (long)(nb + i) * ldb + k0 + 2 * kkw);
        }
    };

    auto stsRegs = [&](int buf) {
        uint32_t w[4];
        #pragma unroll
        for (int i = 0; i < 4; i++)
            w[i] = pack2(fa[2 * i] * ASCALE, fa[2 * i + 1] * ASCALE);
        if (ASRC == A_F32_ROW) {
            *(uint4*)&As[buf][m_a][4 * q_a] = make_uint4(w[0], w[1], w[2], w[3]);
        } else {
            *(uint4*)&As[buf][m_t][kk4] = make_uint4(w[0], w[1], w[2], w[3]);
        }
        if (BSRC == B_F16_KN) {
            // interleave even/odd k rows into half2 words
            uint32_t w0 = __byte_perm(rbh[0].x, rbh[1].x, 0x5410);
            uint32_t w1 = __byte_perm(rbh[0].x, rbh[1].x, 0x7632);
            uint32_t w2 = __byte_perm(rbh[0].y, rbh[1].y, 0x5410);
            uint32_t w3 = __byte_perm(rbh[0].y, rbh[1].y, 0x7632);
            *(uint4*)&Bs[buf][kkb][4 * qb] = make_uint4(w0, w1, w2, w3);
            w0 = __byte_perm(rbh[2].x, rbh[3].x, 0x5410);
            w1 = __byte_perm(rbh[2].x, rbh[3].x, 0x7632);
            w2 = __byte_perm(rbh[2].y, rbh[3].y, 0x5410);
            w3 = __byte_perm(rbh[2].y, rbh[3].y, 0x7632);
            *(uint4*)&Bs[buf][kkb + 1][4 * qb] = make_uint4(w0, w1, w2, w3);
        } else {
            uint32_t v[8];
            #pragma unroll
            for (int i = 0; i < 8; i++) v[i] = pack2(rbf[i].x, rbf[i].y);
            *(uint4*)&Bs[buf][kkw][nb]     = make_uint4(v[0], v[1], v[2], v[3]);
            *(uint4*)&Bs[buf][kkw][nb + 4] = make_uint4(v[4], v[5], v[6], v[7]);
        }
    };

    auto compute = [&](int buf) {
        #pragma unroll
        for (int ks = 0; ks < 2; ks++) {
            const int k8 = ks * 8;
            uint32_t af[2][4];
            #pragma unroll
            for (int mt = 0; mt < 2; mt++) {
                const int mr = wm * 32 + mt * 16 + g;
                af[mt][0] = As[buf][mr][k8 + t];
                af[mt][1] = As[buf][mr + 8][k8 + t];
                af[mt][2] = As[buf][mr][k8 + t + 4];
                af[mt][3] = As[buf][mr + 8][k8 + t + 4];
            }
            uint32_t bf[4][2];
            #pragma unroll
            for (int nt = 0; nt < 4; nt++) {
                const int nc = wn * 32 + nt * 8 + g;
                bf[nt][0] = Bs[buf][k8 + t][nc];
                bf[nt][1] = Bs[buf][k8 + t + 4][nc];
            }
            #pragma unroll
            for (int mt = 0; mt < 2; mt++)
                #pragma unroll
                for (int nt = 0; nt < 4; nt++) {
                    asm volatile(
                        "mma.sync.aligned.m16n8k16.row.col.f32.f16.f16.f32 "
                        "{%0,%1,%2,%3}, {%4,%5,%6,%7}, {%8,%9}, {%0,%1,%2,%3};\n"
                        : "+f"(acc[mt][nt][0]), "+f"(acc[mt][nt][1]),
                          "+f"(acc[mt][nt][2]), "+f"(acc[mt][nt][3])
                        : "r"(af[mt][0]), "r"(af[mt][1]), "r"(af[mt][2]), "r"(af[mt][3]),
                          "r"(bf[nt][0]), "r"(bf[nt][1]));
                }
        }
    };

    const int nk = K / 32;
    loadRegs(0);
    int buf = 0;
    for (int kt = 0; kt < nk; kt++) {
        stsRegs(buf);
        __syncthreads();
        if (kt + 1 < nk) loadRegs((kt + 1) * 32);
        compute(buf);
        buf ^= 1;
    }

    // epilogue
    #pragma unroll
    for (int mt = 0; mt < 2; mt++) {
        #pragma unroll
        for (int nt = 0; nt < 4; nt++) {
            const int row = m0 + wm * 32 + mt * 16 + g;
            const int col = wn * 32 + nt * 8 + 2 * t;
            float x0 = acc[mt][nt][0], x1 = acc[mt][nt][1];
            float x2 = acc[mt][nt][2], x3 = acc[mt][nt][3];
            if (EPI == EPI_SCALE) {
                const float s = 1.f / 4096.f;
                x0 *= s; x1 *= s; x2 *= s; x3 *= s;
            } else {
                const float b0 = __ldg(bias + col);
                const float b1 = __ldg(bias + col + 1);
                x0 += b0; x1 += b1; x2 += b0; x3 += b1;
                if (EPI == EPI_ELU) {
                    x0 = x0 > 0.f ? x0 : expm1f(x0);
                    x1 = x1 > 0.f ? x1 : expm1f(x1);
                    x2 = x2 > 0.f ? x2 : expm1f(x2);
                    x3 = x3 > 0.f ? x3 : expm1f(x3);
                } else {
                    x0 = tanhf(x0); x1 = tanhf(x1);
                    x2 = tanhf(x2); x3 = tanhf(x3);
                }
            }
            if (HOUT) {
                __half* Dh = (__half*)Dv;
                *(uint32_t*)&Dh[(long)row       * ldd + dOff + col] = pack2(x0, x1);
                *(uint32_t*)&Dh[(long)(row + 8) * ldd + dOff + col] = pack2(x2, x3);
            } else {
                float* Df = (float*)Dv;
                *(float2*)&Df[(long)row       * ldd + dOff + col] = make_float2(x0, x1);
                *(float2*)&Df[(long)(row + 8) * ldd + dOff + col] = make_float2(x2, x3);
            }
        }
    }
}

// ===========================================================================
__global__ __launch_bounds__(256, 2)
void proj3_kernel(const float* __restrict__ nodes,
                  const float* __restrict__ W_in,   const float* __restrict__ b_in,
                  const float* __restrict__ W_node, const float* __restrict__ b_node,
                  const float* __restrict__ W_out,  const float* __restrict__ b_out,
                  __half* __restrict__ in_rep, __half* __restrict__ out_rep,
                  float* __restrict__ upd)
{
    const int m0 = blockIdx.x * 64;
    const int z  = blockIdx.z;
    if (z == 0)
        gemm_core<A_F32_ROW, B_F32_NK, EPI_ELU, true >(
            nodes, 128, W_in, 128, b_in, in_rep, 128, 0, 128, m0);
    else if (z == 1)
        gemm_core<A_F32_ROW, B_F32_NK, EPI_ELU, false>(
            nodes, 128, W_node, 128, b_node, upd, 384, 128, 128, m0);
    else
        gemm_core<A_F32_ROW, B_F32_NK, EPI_ELU, true >(
            nodes, 128, W_out, 128, b_out, out_rep, 128, 0, 128, m0);
}

template<bool TA>
__global__ __launch_bounds__(256, 2)
void agg_kernel(const float* __restrict__ adj, const __half* __restrict__ rep,
                float* __restrict__ upd, int dOff)
{
    const long b = blockIdx.y;
    gemm_core<TA ? A_F32_TRANS : A_F32_ROW, B_F16_KN, EPI_SCALE, false>(
        adj + b * (4096l * 4096), 4096,
        rep + b * (4096l * 128), 128,
        nullptr,
        upd + b * (4096l * 384), 384, dOff,
        4096, blockIdx.x * 64);
}

__global__ __launch_bounds__(256, 2)
void final_kernel(const float* __restrict__ upd, const float* __restrict__ W,
                  const float* __restrict__ b, float* __restrict__ out)
{
    gemm_core<A_F32_ROW, B_F32_NK, EPI_TANH, false>(
        upd, 384, W, 384, b, out, 128, 0, 384, blockIdx.x * 64);
}

// ===========================================================================
extern "C" void kernel_launch(void* const* d_in, const int* in_sizes, int n_in,
                              void* d_out, int out_size)
{
    const float* nodes  = (const float*)d_in[0];
    const float* adj    = (const float*)d_in[1];
    const float* W_in   = (const float*)d_in[2];
    const float* b_in   = (const float*)d_in[3];
    const float* W_out  = (const float*)d_in[4];
    const float* b_out  = (const float*)d_in[5];
    const float* W_node = (const float*)d_in[6];
    const float* b_node = (const float*)d_in[7];
    const float* W_upd  = (const float*)d_in[8];
    const float* b_upd  = (const float*)d_in[9];
    float* out = (float*)d_out;

    __half *in_rep, *out_rep;
    float *upd;
    cudaGetSymbolAddress((void**)&in_rep,  g_in_rep);
    cudaGetSymbolAddress((void**)&out_rep, g_out_rep);
    cudaGetSymbolAddress((void**)&upd,     g_upd);

    // 1) three ELU projections (rep outputs fp16)
    proj3_kernel<<<dim3(256, 1, 3), 256>>>(nodes, W_in, b_in, W_node, b_node,
                                           W_out, b_out, in_rep, out_rep, upd);

    // 2) in_agg = adj @ in_rep -> upd[:, 0:128]
    agg_kernel<false><<<dim3(64, 4), 256>>>(adj, in_rep, upd, 0);

    // 3) out_agg = adj^T @ out_rep -> upd[:, 256:384]
    agg_kernel<true><<<dim3(64, 4), 256>>>(adj, out_rep, upd, 256);

    // 4) out = tanh(upd @ W_upd^T + b_upd)
    final_kernel<<<256, 256>>>(upd, W_upd, b_upd, out);
}

// round 6
// speedup vs baseline: 2.1829x; 1.2135x over previous
#include <cuda_runtime.h>
#include <cuda_fp16.h>
#include <cstdint>
#include <cmath>

// ---------------------------------------------------------------------------
// GraphSageLayer: B=4, N=4096, D_IN=128, REP=128, D_OUT=128
//
//  convert: adjh = fp16(adj * 4096)                      (streaming)
//  proj3  : in_rep/out_rep = ELU(nodes@W^T+b) fp16 [n][v]; node_rep->upd fp32
//  agg_in : upd[:,0:128]   = (adjh @ in_rep) / 4096      (cp.async+ldmatrix)
//  agg_outT: T = (out_rep^T(as k-major) @ adjh) / 4096 -> upd[:,256:384] via
//            smem-transposed epilogue  (== adj^T @ out_rep)
//  final  : out = tanh(upd @ W_upd^T + b_upd)
// ---------------------------------------------------------------------------

__device__ __half g_adjh   [4l * 4096 * 4096];  // 134 MB, adj * 4096 in fp16
__device__ __half g_in_rep [4l * 4096 * 128];
__device__ __half g_out_rep[4l * 4096 * 128];
__device__ float  g_upd    [4l * 4096 * 384];

// pack2(a,b): low half = a, high half = b
__device__ __forceinline__ uint32_t pack2(float a, float b) {
    uint32_t r;
    asm("cvt.rn.f16x2.f32 %0, %1, %2;" : "=r"(r) : "f"(b), "f"(a));
    return r;
}
__device__ __forceinline__ void cp16(uint32_t dst, const void* src) {
    asm volatile("cp.async.cg.shared.global [%0], [%1], 16;" :: "r"(dst), "l"(src));
}
__device__ __forceinline__ void cp_commit() {
    asm volatile("cp.async.commit_group;");
}
__device__ __forceinline__ void cp_wait2() {
    asm volatile("cp.async.wait_group 2;");
}
__device__ __forceinline__ void ldsm4(uint32_t* r, uint32_t a) {
    asm volatile("ldmatrix.sync.aligned.m8n8.x4.shared.b16 {%0,%1,%2,%3}, [%4];"
        : "=r"(r[0]), "=r"(r[1]), "=r"(r[2]), "=r"(r[3]) : "r"(a));
}
__device__ __forceinline__ void ldsm4t(uint32_t* r, uint32_t a) {
    asm volatile("ldmatrix.sync.aligned.m8n8.x4.trans.shared.b16 {%0,%1,%2,%3}, [%4];"
        : "=r"(r[0]), "=r"(r[1]), "=r"(r[2]), "=r"(r[3]) : "r"(a));
}
__device__ __forceinline__ void mma16816(float* c, const uint32_t* a,
                                         uint32_t b0, uint32_t b1) {
    asm volatile(
        "mma.sync.aligned.m16n8k16.row.col.f32.f16.f16.f32 "
        "{%0,%1,%2,%3}, {%4,%5,%6,%7}, {%8,%9}, {%0,%1,%2,%3};\n"
        : "+f"(c[0]), "+f"(c[1]), "+f"(c[2]), "+f"(c[3])
        : "r"(a[0]), "r"(a[1]), "r"(a[2]), "r"(a[3]), "r"(b0), "r"(b1));
}

// ===========================================================================
// convert: adjh = fp16(adj * 4096), 8 elems/thread
// ===========================================================================
__global__ __launch_bounds__(1024)
void convert_adj(const float* __restrict__ adj, __half* __restrict__ adjh)
{
    const long i = (long)blockIdx.x * blockDim.x + threadIdx.x;
    const float4* src = (const float4*)adj + i * 2;
    float4 a = src[0], b = src[1];
    uint4 o;
    o.x = pack2(a.x * 4096.f, a.y * 4096.f);
    o.y = pack2(a.z * 4096.f, a.w * 4096.f);
    o.z = pack2(b.x * 4096.f, b.y * 4096.f);
    o.w = pack2(b.z * 4096.f, b.w * 4096.f);
    ((uint4*)adjh)[i] = o;
}

// ===========================================================================
// Aggregation: CTA 128x128, K=4096, BK=32, 4-stage cp.async, ldmatrix frags.
// 8 warps = 2m x 4n, warp tile 64x32.
//  OUTT=false: D[m,v] = sum_k adjh[m0+m][k] * rep[k][v]   -> upd[:,0:128]
//  OUTT=true : D[v,j] = sum_k rep[k][v] * adjh[k][n0+j]   -> upd[:,256:384]^T
// ===========================================================================
template<bool OUTT>
__global__ __launch_bounds__(256)
void agg_pipe(const __half* __restrict__ adjh, const __half* __restrict__ rep,
              float* __restrict__ upd)
{
    extern __shared__ char smem[];
    const int tid  = threadIdx.x;
    const int lane = tid & 31;
    const int warp = tid >> 5;
    const int wm   = warp >> 2;   // 0..1 (m 64 each)
    const int wn   = warp & 3;    // 0..3 (n 32 each)
    const int g    = lane >> 2;
    const int t    = lane & 3;
    const int tile0 = blockIdx.x * 128;   // m0 (in) or n0 (outT)
    const long b   = blockIdx.y;

    const __half* adjB = adjh + b * (4096l * 4096);
    const __half* repB = rep  + b * (4096l * 128);
    float*        updB = upd  + b * (4096l * 384);

    const uint32_t smBase = (uint32_t)__cvta_generic_to_shared(smem);
    constexpr int STAGE = OUTT ? 17408 : 18944;   // bytes per stage
    constexpr int AOFF  = OUTT ? 8704  : 10240;   // B offset within stage

    float acc[4][4][4];
    #pragma unroll
    for (int i = 0; i < 4; i++)
        #pragma unroll
        for (int j = 0; j < 4; j++)
            #pragma unroll
            for (int l = 0; l < 4; l++) acc[i][j][l] = 0.f;

    auto cpTiles = [&](int st, int k0) {
        const uint32_t sA = smBase + st * STAGE;
        const uint32_t sB = sA + AOFF;
        if (!OUTT) {
            // A = adjh rows m: 128 rows x 64B (4 chunks), 80B smem rows
            #pragma unroll
            for (int i = 0; i < 2; i++) {
                const int c = tid + i * 256, row = c >> 2, kc = c & 3;
                cp16(sA + row * 80 + kc * 16,
                     adjB + (long)(tile0 + row) * 4096 + k0 + kc * 8);
            }
            // B = rep rows k: 32 rows x 256B (16 chunks), 272B smem rows
            #pragma unroll
            for (int i = 0; i < 2; i++) {
                const int c = tid + i * 256, k = c >> 4, nc = c & 15;
                cp16(sB + k * 272 + nc * 16,
                     repB + (long)(k0 + k) * 128 + nc * 8);
            }
        } else {
            #pragma unroll
            for (int i = 0; i < 2; i++) {
                const int c = tid + i * 256, k = c >> 4, nc = c & 15;
                // A = rep rows k (k-major for m=v)
                cp16(sA + k * 272 + nc * 16,
                     repB + (long)(k0 + k) * 128 + nc * 8);
                // B = adjh rows k, cols n0..n0+127
                cp16(sB + k * 272 + nc * 16,
                     adjB + (long)(k0 + k) * 4096 + tile0 + nc * 8);
            }
        }
    };

    auto compute = [&](int st) {
        const uint32_t sA = smBase + st * STAGE;
        const uint32_t sB = sA + AOFF;
        #pragma unroll
        for (int ks = 0; ks < 2; ks++) {
            uint32_t aF[4][4], bF[2][4];
            #pragma unroll
            for (int mt = 0; mt < 4; mt++) {
                if (!OUTT) {
                    ldsm4(aF[mt], sA + (wm * 64 + mt * 16 + (lane & 15)) * 80
                                     + ((lane >> 4) + 2 * ks) * 16);
                } else {
                    ldsm4t(aF[mt], sA + ((lane & 7) + (lane >> 4) * 8 + 16 * ks) * 272
                                      + (wm * 64 + mt * 16 + ((lane >> 3) & 1) * 8) * 2);
                }
            }
            #pragma unroll
            for (int nt = 0; nt < 2; nt++)
                ldsm4t(bF[nt], sB + ((lane & 15) + 16 * ks) * 272
                                  + wn * 64 + nt * 32 + (lane >> 4) * 16);
            #pragma unroll
            for (int mt = 0; mt < 4; mt++)
                #pragma unroll
                for (int n8 = 0; n8 < 4; n8++)
                    mma16816(acc[mt][n8], aF[mt],
                             bF[n8 >> 1][(n8 & 1) * 2], bF[n8 >> 1][(n8 & 1) * 2 + 1]);
        }
    };

    // prologue: fill 3 stages
    #pragma unroll
    for (int s = 0; s < 3; s++) { cpTiles(s, s * 32); cp_commit(); }

    #pragma unroll 1
    for (int kt = 0; kt < 128; kt++) {
        cp_wait2();
        __syncthreads();
        const int nx = kt + 3;
        if (nx < 128) cpTiles(nx & 3, nx * 32);
        cp_commit();                 // empty groups near the tail keep wait-count math uniform
        compute(kt & 3);
    }

    const float s = 1.f / 4096.f;
    if (!OUTT) {
        #pragma unroll
        for (int mt = 0; mt < 4; mt++)
            #pragma unroll
            for (int n8 = 0; n8 < 4; n8++) {
                const int row = tile0 + wm * 64 + mt * 16 + g;
                const int col = wn * 32 + n8 * 8 + 2 * t;
                *(float2*)&updB[(long)row * 384 + col] =
                    make_float2(acc[mt][n8][0] * s, acc[mt][n8][1] * s);
                *(float2*)&updB[(long)(row + 8) * 384 + col] =
                    make_float2(acc[mt][n8][2] * s, acc[mt][n8][3] * s);
            }
    } else {
        // transpose 128x128 tile through smem, write upd[tile0+j][256+v] coalesced
        __syncthreads();
        float* fsm = (float*)smem;   // [v][132] = 67584 B, fits in 69632 B alloc
        #pragma unroll
        for (int mt = 0; mt < 4; mt++)
            #pragma unroll
            for (int n8 = 0; n8 < 4; n8++) {
                const int v = wm * 64 + mt * 16 + g;
                const int j = wn * 32 + n8 * 8 + 2 * t;
                fsm[v * 132 + j]           = acc[mt][n8][0] * s;
                fsm[v * 132 + j + 1]       = acc[mt][n8][1] * s;
                fsm[(v + 8) * 132 + j]     = acc[mt][n8][2] * s;
                fsm[(v + 8) * 132 + j + 1] = acc[mt][n8][3] * s;
            }
        __syncthreads();
        const int j  = tid >> 1;
        const int vb = (tid & 1) * 64;
        float* dst = &updB[(long)(tile0 + j) * 384 + 256 + vb];
        #pragma unroll
        for (int i = 0; i < 16; i++) {
            const int v = vb + i * 4;
            ((float4*)dst)[i] = make_float4(
                fsm[v * 132 + j],       fsm[(v + 1) * 132 + j],
                fsm[(v + 2) * 132 + j], fsm[(v + 3) * 132 + j]);
        }
    }
}

// ===========================================================================
// mma.sync fp16 GEMM for proj / final (small K): CTA 64x128, BK=32.
// ===========================================================================
#define AROW 20
#define BROW 136
enum { EPI_ELU = 1, EPI_TANH = 2 };

template<int EPI, bool HOUT>
__device__ __forceinline__ void gemm_core(
    const float* __restrict__ Af, int lda,
    const float* __restrict__ Bf, int ldb,     // B: NxK row-major (TN)
    const float* __restrict__ bias,
    void* __restrict__ Dv, int ldd, int dOff,
    int K, int m0)
{
    __shared__ uint32_t As[2][64][AROW];
    __shared__ uint32_t Bs[2][16][BROW];

    const int tid  = threadIdx.x;
    const int lane = tid & 31;
    const int warp = tid >> 5;
    const int wm   = warp >> 2;
    const int wn   = warp & 3;
    const int g    = lane >> 2;
    const int t    = lane & 3;

    float acc[2][4][4];
    #pragma unroll
    for (int i = 0; i < 2; i++)
        #pragma unroll
        for (int j = 0; j < 4; j++)
            #pragma unroll
            for (int l = 0; l < 4; l++) acc[i][j][l] = 0.f;

    const int m_a = tid >> 2, q_a = tid & 3;
    const int kkw = tid & 15, nb = (tid >> 4) * 8;

    float fa[8];
    float2 rbf[8];

    auto loadRegs = [&](int k0) {
        const float4* p = (const float4*)(Af + (long)(m0 + m_a) * lda + k0 + 8 * q_a);
        float4 v0 = p[0], v1 = p[1];
        fa[0] = v0.x; fa[1] = v0.y; fa[2] = v0.z; fa[3] = v0.w;
        fa[4] = v1.x; fa[5] = v1.y; fa[6] = v1.z; fa[7] = v1.w;
        #pragma unroll
        for (int i = 0; i < 8; i++)
            rbf[i] = *(const float2*)(Bf + (long)(nb + i) * ldb + k0 + 2 * kkw);
    };
    auto stsRegs = [&](int buf) {
        uint32_t w[4];
        #pragma unroll
        for (int i = 0; i < 4; i++) w[i] = pack2(fa[2 * i], fa[2 * i + 1]);
        *(uint4*)&As[buf][m_a][4 * q_a] = make_uint4(w[0], w[1], w[2], w[3]);
        uint32_t v[8];
        #pragma unroll
        for (int i = 0; i < 8; i++) v[i] = pack2(rbf[i].x, rbf[i].y);
        *(uint4*)&Bs[buf][kkw][nb]     = make_uint4(v[0], v[1], v[2], v[3]);
        *(uint4*)&Bs[buf][kkw][nb + 4] = make_uint4(v[4], v[5], v[6], v[7]);
    };
    auto compute = [&](int buf) {
        #pragma unroll
        for (int ks = 0; ks < 2; ks++) {
            const int k8 = ks * 8;
            uint32_t af[2][4];
            #pragma unroll
            for (int mt = 0; mt < 2; mt++) {
                const int mr = wm * 32 + mt * 16 + g;
                af[mt][0] = As[buf][mr][k8 + t];
                af[mt][1] = As[buf][mr + 8][k8 + t];
                af[mt][2] = As[buf][mr][k8 + t + 4];
                af[mt][3] = As[buf][mr + 8][k8 + t + 4];
            }
            #pragma unroll
            for (int nt = 0; nt < 4; nt++) {
                const int nc = wn * 32 + nt * 8 + g;
                mma16816(acc[0][nt], af[0], Bs[buf][k8 + t][nc], Bs[buf][k8 + t + 4][nc]);
                mma16816(acc[1][nt], af[1], Bs[buf][k8 + t][nc], Bs[buf][k8 + t + 4][nc]);
            }
        }
    };

    const int nk = K / 32;
    loadRegs(0);
    int buf = 0;
    for (int kt = 0; kt < nk; kt++) {
        stsRegs(buf);
        __syncthreads();
        if (kt + 1 < nk) loadRegs((kt + 1) * 32);
        compute(buf);
        buf ^= 1;
    }

    #pragma unroll
    for (int mt = 0; mt < 2; mt++) {
        #pragma unroll
        for (int nt = 0; nt < 4; nt++) {
            const int row = m0 + wm * 32 + mt * 16 + g;
            const int col = wn * 32 + nt * 8 + 2 * t;
            const float b0 = __ldg(bias + col);
            const float b1 = __ldg(bias + col + 1);
            float x0 = acc[mt][nt][0] + b0, x1 = acc[mt][nt][1] + b1;
            float x2 = acc[mt][nt][2] + b0, x3 = acc[mt][nt][3] + b1;
            if (EPI == EPI_ELU) {
                x0 = x0 > 0.f ? x0 : expm1f(x0);
                x1 = x1 > 0.f ? x1 : expm1f(x1);
                x2 = x2 > 0.f ? x2 : expm1f(x2);
                x3 = x3 > 0.f ? x3 : expm1f(x3);
            } else {
                x0 = tanhf(x0); x1 = tanhf(x1);
                x2 = tanhf(x2); x3 = tanhf(x3);
            }
            if (HOUT) {
                __half* Dh = (__half*)Dv;
                *(uint32_t*)&Dh[(long)row       * ldd + dOff + col] = pack2(x0, x1);
                *(uint32_t*)&Dh[(long)(row + 8) * ldd + dOff + col] = pack2(x2, x3);
            } else {
                float* Df = (float*)Dv;
                *(float2*)&Df[(long)row       * ldd + dOff + col] = make_float2(x0, x1);
                *(float2*)&Df[(long)(row + 8) * ldd + dOff + col] = make_float2(x2, x3);
            }
        }
    }
}

__global__ __launch_bounds__(256, 2)
void proj3_kernel(const float* __restrict__ nodes,
                  const float* __restrict__ W_in,   const float* __restrict__ b_in,
                  const float* __restrict__ W_node, const float* __restrict__ b_node,
                  const float* __restrict__ W_out,  const float* __restrict__ b_out,
                  __half* __restrict__ in_rep, __half* __restrict__ out_rep,
                  float* __restrict__ upd)
{
    const int m0 = blockIdx.x * 64;
    const int z  = blockIdx.z;
    if (z == 0)
        gemm_core<EPI_ELU, true >(nodes, 128, W_in,   128, b_in,   in_rep,  128, 0,   128, m0);
    else if (z == 1)
        gemm_core<EPI_ELU, false>(nodes, 128, W_node, 128, b_node, upd,     384, 128, 128, m0);
    else
        gemm_core<EPI_ELU, true >(nodes, 128, W_out,  128, b_out,  out_rep, 128, 0,   128, m0);
}

__global__ __launch_bounds__(256, 2)
void final_kernel(const float* __restrict__ upd, const float* __restrict__ W,
                  const float* __restrict__ b, float* __restrict__ out)
{
    gemm_core<EPI_TANH, false>(upd, 384, W, 384, b, out, 128, 0, 384, blockIdx.x * 64);
}

// ===========================================================================
extern "C" void kernel_launch(void* const* d_in, const int* in_sizes, int n_in,
                              void* d_out, int out_size)
{
    const float* nodes  = (const float*)d_in[0];
    const float* adj    = (const float*)d_in[1];
    const float* W_in   = (const float*)d_in[2];
    const float* b_in   = (const float*)d_in[3];
    const float* W_out  = (const float*)d_in[4];
    const float* b_out  = (const float*)d_in[5];
    const float* W_node = (const float*)d_in[6];
    const float* b_node = (const float*)d_in[7];
    const float* W_upd  = (const float*)d_in[8];
    const float* b_upd  = (const float*)d_in[9];
    float* out = (float*)d_out;

    __half *adjh, *in_rep, *out_rep;
    float *upd;
    cudaGetSymbolAddress((void**)&adjh,    g_adjh);
    cudaGetSymbolAddress((void**)&in_rep,  g_in_rep);
    cudaGetSymbolAddress((void**)&out_rep, g_out_rep);
    cudaGetSymbolAddress((void**)&upd,     g_upd);

    const int SMEM_IN  = 4 * 18944;   // 75776: 4-stage pipeline (in_agg)
    const int SMEM_OUT = 4 * 17408;   // 69632: 4-stage pipeline (>= 67584 transpose buf)
    cudaFuncSetAttribute(agg_pipe<false>,
                         cudaFuncAttributeMaxDynamicSharedMemorySize, SMEM_IN);
    cudaFuncSetAttribute(agg_pipe<true>,
                         cudaFuncAttributeMaxDynamicSharedMemorySize, SMEM_OUT);

    // 0) adjh = fp16(adj * 4096)
    convert_adj<<<8192, 1024>>>(adj, adjh);

    // 1) three ELU projections (rep outputs fp16 row-major [n][v])
    proj3_kernel<<<dim3(256, 1, 3), 256>>>(nodes, W_in, b_in, W_node, b_node,
                                           W_out, b_out, in_rep, out_rep, upd);

    // 2) in_agg  -> upd[:, 0:128]
    agg_pipe<false><<<dim3(32, 4), 256, SMEM_IN>>>(adjh, in_rep, upd);

    // 3) out_agg -> upd[:, 256:384] (transposed-product formulation)
    agg_pipe<true><<<dim3(32, 4), 256, SMEM_OUT>>>(adjh, out_rep, upd);

    // 4) out = tanh(upd @ W_upd^T + b_upd)
    final_kernel<<<256, 256>>>(upd, W_upd, b_upd, out);
}